// round 8
// baseline (speedup 1.0000x reference)
#include <cuda_runtime.h>
#include <math.h>

// ---------------- problem constants ----------------
#define BQ    8
#define CIMG  256
#define CTXT  768
#define NHEAD 8
#define HDIM  32
#define LTXT  77
#define NTOK  13824          // 24*24*24
#define TOTAL (BQ*CIMG*NTOK) // 28,311,552

// ---------------- device scratch (no allocations allowed) ----------------
__device__ float g_WqT[CIMG*CIMG];   // [c][i]  fused in_q_w @ q_proj_w, transposed
__device__ float g_WkT[CTXT*CIMG];   // [t][i]  fused in_k_w @ k_proj_w, transposed
__device__ float g_WvT[CTXT*CIMG];   // [t][i]
__device__ float g_WoT[CIMG*CIMG];   // [i][co] fused out_conv_w @ out_proj_w, transposed
__device__ float g_biaso[CIMG];      // out_conv_w@out_proj_b + out_conv_b
__device__ float g_KH[BQ*LTXT*CIMG]; // [b,l,i]
__device__ float g_VH[BQ*LTXT*CIMG];
__device__ float g_Q [BQ*NTOK*CIMG]; // [b,h,n,hd]  HEAD-MAJOR for coalesced attention reads
__device__ float g_OT[BQ*CIMG*NTOK]; // [b,i,n]  (attention output, channel-major)
__device__ float g_R [BQ*CIMG*NTOK]; // [b,c,n]  residual sum pre-norm
__device__ float g_psum[BQ*CIMG];
__device__ float g_psumsq[BQ*CIMG];
__device__ float g_mean[BQ*CIMG];
__device__ float g_rstd[BQ*CIMG];
__device__ unsigned char g_mask[BQ*LTXT];  // normalized mask (dtype-agnostic)

// cp.async helpers (sm_80+; native LDGSTS on sm_103a)
#define CP_ASYNC16(smem_u32, gptr) \
    asm volatile("cp.async.cg.shared.global [%0], [%1], 16;\n" :: "r"(smem_u32), "l"(gptr))
#define CP_COMMIT()  asm volatile("cp.async.commit_group;\n" ::: "memory")
#define CP_WAIT0()   asm volatile("cp.async.wait_group 0;\n" ::: "memory")

// packed f32x2 FMA (Blackwell): d = a*b + d on two lanes at once
#define FFMA2(d, a, b) \
    asm("fma.rn.f32x2 %0, %1, %2, %0;" : "+l"(d) : "l"(a), "l"(b))
#define PACK2_BCAST(d, f) \
    asm("mov.b64 %0, {%1, %1};" : "=l"(d) : "r"(__float_as_uint(f)))

__device__ __forceinline__ unsigned smem_u32(const void* p) {
    return (unsigned)__cvta_generic_to_shared(p);
}
__device__ __forceinline__ float ull_lo(unsigned long long v) {
    return __uint_as_float((unsigned)(v & 0xffffffffull));
}
__device__ __forceinline__ float ull_hi(unsigned long long v) {
    return __uint_as_float((unsigned)(v >> 32));
}

// ---------------- mask normalization: accept uint8 OR int32 bool encoding ----
// Mask rows are guaranteed monotone 0-prefix / 1-suffix with last element 1
// (lengths in [40,77)). The uint8 interpretation of int32-encoded data yields
// "1,0,0,0" byte patterns that violate monotonicity, so the check is decisive.
__global__ void k_mask(const unsigned char* __restrict__ mraw) {
    __shared__ int s_ok;
    if (threadIdx.x == 0) s_ok = 1;
    __syncthreads();
    int b = threadIdx.x;
    if (b < BQ) {
        int prev = 0, ok = 1;
        for (int l = 0; l < LTXT; l++) {
            int v = mraw[b*LTXT + l];
            if (v > 1 || v < prev) { ok = 0; break; }
            prev = v;
        }
        if (ok && mraw[b*LTXT + LTXT - 1] != 1) ok = 0;  // last key always padded
        if (!ok) atomicExch(&s_ok, 0);
    }
    __syncthreads();
    if (b < BQ) {
        const int* m32 = (const int*)mraw;
        for (int l = 0; l < LTXT; l++) {
            g_mask[b*LTXT + l] = s_ok ? mraw[b*LTXT + l]
                                      : (unsigned char)(m32[b*LTXT + l] != 0);
        }
    }
}

// ---------------- tiny kernels: weight fusion ----------------
__global__ void k_zero_stats() {
    int i = blockIdx.x * 256 + threadIdx.x;
    if (i < BQ*CIMG) { g_psum[i] = 0.f; g_psumsq[i] = 0.f; }
}

// WqT[c,i] = sum_o in_q_w[i,o] * q_proj_w[o,c]
__global__ void k_wq(const float* __restrict__ in_q_w, const float* __restrict__ q_proj_w) {
    int c = blockIdx.x, i = threadIdx.x;
    float s = 0.f;
    for (int o = 0; o < CIMG; o++) s += in_q_w[i*CIMG + o] * q_proj_w[o*CIMG + c];
    g_WqT[c*CIMG + i] = s;
}

// WkT[t,i] = sum_c in_k_w[i,c] * k_proj_w[c,t]   (k_proj_w is [CIMG, CTXT])
__global__ void k_wkv(const float* __restrict__ in_w, const float* __restrict__ proj_w, float* __restrict__ out) {
    int t = blockIdx.x, i = threadIdx.x;
    float s = 0.f;
    for (int c = 0; c < CIMG; c++) s += in_w[i*CIMG + c] * proj_w[c*CTXT + t];
    out[t*CIMG + i] = s;
}

// WoT[i,co] = sum_j out_conv_w[co,j] * out_proj_w[j,i]
__global__ void k_wo(const float* __restrict__ out_conv_w, const float* __restrict__ out_proj_w) {
    int i = blockIdx.x, co = threadIdx.x;
    float s = 0.f;
    for (int j = 0; j < CIMG; j++) s += out_conv_w[co*CIMG + j] * out_proj_w[j*CIMG + i];
    g_WoT[i*CIMG + co] = s;
}

__global__ void k_biaso(const float* __restrict__ out_conv_w, const float* __restrict__ out_proj_b,
                        const float* __restrict__ out_conv_b) {
    int co = threadIdx.x;
    float s = out_conv_b[co];
    for (int j = 0; j < CIMG; j++) s += out_conv_w[co*CIMG + j] * out_proj_b[j];
    g_biaso[co] = s;
}

// ---------------- K/V projection: 8 text tokens per block (weight reuse x8) ----
#define KVTOK 8
__global__ __launch_bounds__(256)
void k_kv(const float* __restrict__ x_txt,
          const float* __restrict__ in_k_b, const float* __restrict__ in_v_b) {
    int b  = blockIdx.x / ((LTXT + KVTOK - 1) / KVTOK);
    int c0 = blockIdx.x % ((LTXT + KVTOK - 1) / KVTOK);
    int l0 = c0 * KVTOK;
    int nt = min(KVTOK, LTXT - l0);

    __shared__ float xr[KVTOK][CTXT];
    for (int idx = threadIdx.x; idx < nt * CTXT; idx += 256) {
        int j = idx / CTXT, t = idx % CTXT;
        xr[j][t] = x_txt[((long)b * LTXT + l0 + j) * CTXT + t];
    }
    __syncthreads();

    int i = threadIdx.x;
    float bk = in_k_b[i], bv = in_v_b[i];
    float sk[KVTOK], sv[KVTOK];
#pragma unroll
    for (int j = 0; j < KVTOK; j++) { sk[j] = bk; sv[j] = bv; }

    for (int t = 0; t < CTXT; t++) {
        float wk = g_WkT[t*CIMG + i];
        float wv = g_WvT[t*CIMG + i];
#pragma unroll
        for (int j = 0; j < KVTOK; j++) {
            float x = xr[j][t];
            sk[j] += x * wk;
            sv[j] += x * wv;
        }
    }
    for (int j = 0; j < nt; j++) {
        long o = ((long)b * LTXT + l0 + j) * CIMG + i;
        g_KH[o] = sk[j];
        g_VH[o] = sv[j];
    }
}

// ---------------- main GEMM: C[M,Nc] = sum_k A[k,m] * B[k,n]  (both k-major) ----------------
// 128x128 tile, BK=16, 256 threads, 8x8 per thread (as 8x4 packed f32x2 pairs).
// cp.async ping-pong double buffer: ONE __syncthreads per k-iteration.
// Inner loop uses fma.rn.f32x2 (FFMA2): 32 packed FMAs per k-slice instead of 64 scalar.
// EPI=0: Q store, HEAD-MAJOR: Q[((h)*NTOK + row)*32 + hd] = acc + biasN[col]
// EPI=1: C = acc + g_biaso[row] + resid;  accumulate per-row sum/sumsq into g_psum/g_psumsq
#define GBM 128
#define GBN 128
#define GBK 16

template<int EPI>
__global__ __launch_bounds__(256)
void gemm_kn(const float* __restrict__ Ab, const float* __restrict__ Bb, float* __restrict__ Cb,
             int M, int Nc, int K, int lda, int ldb, int ldc,
             long sA, long sB, long sC,
             const float* __restrict__ biasN,
             const float* __restrict__ residB, long sR)
{
    int bz = blockIdx.z;
    const float* A = Ab + (long)bz * sA;
    const float* B = Bb + (long)bz * sB;
    float*       C = Cb + (long)bz * sC;

    __shared__ float As[2][GBK][GBM];
    __shared__ float Bs[2][GBK][GBN];

    int bm  = blockIdx.y * GBM;
    int bn  = blockIdx.x * GBN;
    int tid = threadIdx.x;
    int lr  = tid >> 5;           // 0..7  (k row within tile; also handles lr+8)
    int lc  = (tid & 31) << 2;    // col*4
    int ty  = tid >> 4;           // 0..15
    int tx  = tid & 15;           // 0..15

    unsigned long long acc[8][4]; // 8 rows x 4 packed column-pairs (f32x2)
#pragma unroll
    for (int i = 0; i < 8; i++)
#pragma unroll
        for (int jp = 0; jp < 4; jp++) acc[i][jp] = 0ull;

    // async-load first k-tile into buffer 0
    CP_ASYNC16(smem_u32(&As[0][lr    ][lc]), &A[(long)(lr    ) * lda + bm + lc]);
    CP_ASYNC16(smem_u32(&As[0][lr + 8][lc]), &A[(long)(lr + 8) * lda + bm + lc]);
    CP_ASYNC16(smem_u32(&Bs[0][lr    ][lc]), &B[(long)(lr    ) * ldb + bn + lc]);
    CP_ASYNC16(smem_u32(&Bs[0][lr + 8][lc]), &B[(long)(lr + 8) * ldb + bn + lc]);
    CP_COMMIT();
    CP_WAIT0();
    __syncthreads();

    int buf = 0;
    for (int k0 = 0; k0 < K; k0 += GBK) {
        bool more = (k0 + GBK < K);
        if (more) {
            int nb = buf ^ 1;
            CP_ASYNC16(smem_u32(&As[nb][lr    ][lc]), &A[(long)(k0 + GBK + lr    ) * lda + bm + lc]);
            CP_ASYNC16(smem_u32(&As[nb][lr + 8][lc]), &A[(long)(k0 + GBK + lr + 8) * lda + bm + lc]);
            CP_ASYNC16(smem_u32(&Bs[nb][lr    ][lc]), &B[(long)(k0 + GBK + lr    ) * ldb + bn + lc]);
            CP_ASYNC16(smem_u32(&Bs[nb][lr + 8][lc]), &B[(long)(k0 + GBK + lr + 8) * ldb + bn + lc]);
            CP_COMMIT();
        }

#pragma unroll
        for (int kk = 0; kk < GBK; kk++) {
            unsigned long long rbp[4];
#pragma unroll
            for (int jp = 0; jp < 4; jp++)
                rbp[jp] = *reinterpret_cast<const unsigned long long*>(&Bs[buf][kk][tx*8 + jp*2]);
#pragma unroll
            for (int i = 0; i < 8; i++) {
                unsigned long long rap;
                PACK2_BCAST(rap, As[buf][kk][ty*8 + i]);
#pragma unroll
                for (int jp = 0; jp < 4; jp++)
                    FFMA2(acc[i][jp], rap, rbp[jp]);
            }
        }

        if (more) {
            CP_WAIT0();
            __syncthreads();
            buf ^= 1;
        }
    }

    if (EPI == 0) {
        // head-major Q store: row = token n, col = channel i = h*32 + hd
#pragma unroll
        for (int i = 0; i < 8; i++) {
            int row = bm + ty*8 + i;
#pragma unroll
            for (int jp = 0; jp < 4; jp++) {
                float v0 = ull_lo(acc[i][jp]);
                float v1 = ull_hi(acc[i][jp]);
                int col0 = bn + tx*8 + jp*2;
                int col1 = col0 + 1;
                C[((long)(col0 >> 5) * NTOK + row) * HDIM + (col0 & 31)] = v0 + biasN[col0];
                C[((long)(col1 >> 5) * NTOK + row) * HDIM + (col1 & 31)] = v1 + biasN[col1];
            }
        }
    } else {
        const float* resid = residB + (long)bz * sR;
#pragma unroll
        for (int i = 0; i < 8; i++) {
            int row = bm + ty*8 + i;     // channel co (M=256)
            float bM = g_biaso[row];
            float rs = 0.f, rss = 0.f;
#pragma unroll
            for (int jp = 0; jp < 4; jp++) {
                int col0 = bn + tx*8 + jp*2;
                float v0 = ull_lo(acc[i][jp]) + bM + resid[(long)row * ldc + col0];
                float v1 = ull_hi(acc[i][jp]) + bM + resid[(long)row * ldc + col0 + 1];
                C[(long)row * ldc + col0]     = v0;
                C[(long)row * ldc + col0 + 1] = v1;
                rs  += v0 + v1;
                rss += v0 * v0 + v1 * v1;
            }
            // reduce across the 16 tx lanes (shuffle width 16)
#pragma unroll
            for (int off = 8; off >= 1; off >>= 1) {
                rs  += __shfl_down_sync(0xffffffffu, rs,  off, 16);
                rss += __shfl_down_sync(0xffffffffu, rss, off, 16);
            }
            if (tx == 0) {
                atomicAdd(&g_psum[bz*CIMG + row],   rs);
                atomicAdd(&g_psumsq[bz*CIMG + row], rss);
            }
        }
    }
}

// ---------------- attention: one thread per query token, flash-style over L=77 ----------------
// Q is head-major [b,h,n,hd] so the per-thread q load is fully coalesced.
__global__ __launch_bounds__(256)
void k_attn() {
    int b = blockIdx.z, h = blockIdx.y;
    int n = blockIdx.x * 256 + threadIdx.x;

    __shared__ float Kh[LTXT][HDIM];
    __shared__ float Vh[LTXT][HDIM];
    __shared__ unsigned char ms[LTXT];

    for (int idx = threadIdx.x; idx < LTXT*HDIM; idx += 256) {
        int l = idx >> 5, j = idx & 31;
        Kh[l][j] = g_KH[(b*LTXT + l)*CIMG + h*HDIM + j];
        Vh[l][j] = g_VH[(b*LTXT + l)*CIMG + h*HDIM + j];
    }
    if (threadIdx.x < LTXT) ms[threadIdx.x] = g_mask[b*LTXT + threadIdx.x];
    __syncthreads();

    float q[HDIM];
    const float4* qp = reinterpret_cast<const float4*>(
        &g_Q[(((long)b * NHEAD + h) * NTOK + n) * HDIM]);
#pragma unroll
    for (int j4 = 0; j4 < 8; j4++) {
        float4 t = qp[j4];
        q[j4*4+0] = t.x; q[j4*4+1] = t.y; q[j4*4+2] = t.z; q[j4*4+3] = t.w;
    }

    float m = -1e30f, sum = 0.f;
    float o[HDIM];
#pragma unroll
    for (int j = 0; j < HDIM; j++) o[j] = 0.f;

    for (int l = 0; l < LTXT; l++) {
        if (ms[l]) continue;                  // uniform across block (per-batch mask)
        float s = 0.f;
#pragma unroll
        for (int j = 0; j < HDIM; j++) s += q[j] * Kh[l][j];
        s *= 0.17677669529663687f;            // 1/sqrt(32)
        float mn   = fmaxf(m, s);
        float corr = __expf(m - mn);
        float p    = __expf(s - mn);
        sum = sum * corr + p;
#pragma unroll
        for (int j = 0; j < HDIM; j++) o[j] = o[j] * corr + p * Vh[l][j];
        m = mn;
    }
    float inv = 1.f / sum;
    int obase = (b*CIMG + h*HDIM) * NTOK + n;
#pragma unroll
    for (int j = 0; j < HDIM; j++) g_OT[obase + j*NTOK] = o[j] * inv;
}

// ---------------- norm stats + finalize ----------------
__global__ void k_stats() {
    int i = blockIdx.x * 256 + threadIdx.x;
    if (i < BQ*CIMG) {
        float mu  = g_psum[i]   * (1.f / NTOK);
        float var = g_psumsq[i] * (1.f / NTOK) - mu * mu;
        g_mean[i] = mu;
        g_rstd[i] = rsqrtf(var + 1e-5f);
    }
}

__global__ __launch_bounds__(256)
void k_final(const float* __restrict__ nw, const float* __restrict__ nb, float* __restrict__ out) {
    int i4 = blockIdx.x * 256 + threadIdx.x;   // < TOTAL/4
    int i  = i4 * 4;
    int bc = i / NTOK;                         // NTOK % 4 == 0, so one (b,c) per float4
    int c  = bc & (CIMG - 1);
    float mu = g_mean[bc], rs = g_rstd[bc], w = nw[c], bb = nb[c];
    float4 r = *reinterpret_cast<const float4*>(&g_R[i]);
    float4 o;
    float v;
    v = (r.x - mu) * rs * w + bb; o.x = v / (1.f + __expf(-v));
    v = (r.y - mu) * rs * w + bb; o.y = v / (1.f + __expf(-v));
    v = (r.z - mu) * rs * w + bb; o.z = v / (1.f + __expf(-v));
    v = (r.w - mu) * rs * w + bb; o.w = v / (1.f + __expf(-v));
    *reinterpret_cast<float4*>(&out[i]) = o;
}

// ---------------- launch ----------------
extern "C" void kernel_launch(void* const* d_in, const int* in_sizes, int n_in,
                              void* d_out, int out_size) {
    const float* x_img      = (const float*)d_in[0];
    const float* x_txt      = (const float*)d_in[1];
    const unsigned char* txt_mask = (const unsigned char*)d_in[2];
    const float* q_proj_w   = (const float*)d_in[3];
    const float* k_proj_w   = (const float*)d_in[4];
    const float* v_proj_w   = (const float*)d_in[5];
    const float* in_q_w     = (const float*)d_in[6];
    const float* in_q_b     = (const float*)d_in[7];
    const float* in_k_w     = (const float*)d_in[8];
    const float* in_k_b     = (const float*)d_in[9];
    const float* in_v_w     = (const float*)d_in[10];
    const float* in_v_b     = (const float*)d_in[11];
    const float* out_proj_w = (const float*)d_in[12];
    const float* out_proj_b = (const float*)d_in[13];
    const float* out_conv_w = (const float*)d_in[14];
    const float* out_conv_b = (const float*)d_in[15];
    const float* norm_w     = (const float*)d_in[16];
    const float* norm_b     = (const float*)d_in[17];
    float* out = (float*)d_out;

    float *pWqT, *pWkT, *pWvT, *pWoT, *pQ, *pOT, *pR;
    cudaGetSymbolAddress((void**)&pWqT, g_WqT);
    cudaGetSymbolAddress((void**)&pWkT, g_WkT);
    cudaGetSymbolAddress((void**)&pWvT, g_WvT);
    cudaGetSymbolAddress((void**)&pWoT, g_WoT);
    cudaGetSymbolAddress((void**)&pQ,   g_Q);
    cudaGetSymbolAddress((void**)&pOT,  g_OT);
    cudaGetSymbolAddress((void**)&pR,   g_R);

    k_zero_stats<<<(BQ*CIMG + 255)/256, 256>>>();
    k_mask<<<1, 32>>>(txt_mask);

    // fused weights
    k_wq   <<<CIMG, CIMG>>>(in_q_w, q_proj_w);
    k_wkv  <<<CTXT, CIMG>>>(in_k_w, k_proj_w, pWkT);
    k_wkv  <<<CTXT, CIMG>>>(in_v_w, v_proj_w, pWvT);
    k_wo   <<<CIMG, CIMG>>>(out_conv_w, out_proj_w);
    k_biaso<<<1,    CIMG>>>(out_conv_w, out_proj_b, out_conv_b);

    // K/V heads (8 tokens per block for weight reuse)
    k_kv<<<BQ * ((LTXT + KVTOK - 1) / KVTOK), 256>>>(x_txt, in_k_b, in_v_b);

    // Q = x_img^T @ Wq^T + bq  -> g_Q [b,h,n,hd] head-major
    {
        dim3 grid(CIMG/GBN, NTOK/GBM, BQ);
        gemm_kn<0><<<grid, 256>>>(x_img, pWqT, pQ,
                                  NTOK, CIMG, CIMG,
                                  NTOK, CIMG, CIMG,
                                  (long)CIMG*NTOK, 0L, (long)NTOK*CIMG,
                                  in_q_b, nullptr, 0L);
    }

    // attention -> g_OT [b,i,n]
    {
        dim3 grid(NTOK/256, NHEAD, BQ);
        k_attn<<<grid, 256>>>();
    }

    // R = Wo @ O + bias_o + x_img  -> g_R [b,c,n]  (+ per-channel stats)
    {
        dim3 grid(NTOK/GBN, CIMG/GBM, BQ);
        gemm_kn<1><<<grid, 256>>>(pWoT, pOT, pR,
                                  CIMG, NTOK, CIMG,
                                  CIMG, NTOK, NTOK,
                                  0L, (long)CIMG*NTOK, (long)CIMG*NTOK,
                                  nullptr, x_img, (long)CIMG*NTOK);
    }

    k_stats<<<(BQ*CIMG + 255)/256, 256>>>();
    k_final<<<TOTAL/1024, 256>>>(norm_w, norm_b, out);
}

// round 11
// speedup vs baseline: 1.5348x; 1.5348x over previous
#include <cuda_runtime.h>
#include <math.h>

// ---------------- problem constants ----------------
#define BQ    8
#define CIMG  256
#define CTXT  768
#define NHEAD 8
#define HDIM  32
#define LTXT  77
#define NTOK  13824          // 24*24*24
#define TOTAL (BQ*CIMG*NTOK) // 28,311,552

// ---------------- device scratch (no allocations allowed) ----------------
__device__ float g_WqT[CIMG*CIMG];   // [c][i]  fused in_q_w @ q_proj_w, transposed
__device__ float g_WkT[CTXT*CIMG];   // [t][i]  fused in_k_w @ k_proj_w, transposed
__device__ float g_WvT[CTXT*CIMG];   // [t][i]
__device__ float g_WoT[CIMG*CIMG];   // [i][co] fused out_conv_w @ out_proj_w, transposed
__device__ float g_biaso[CIMG];      // out_conv_w@out_proj_b + out_conv_b
__device__ float g_iqT[CIMG*CIMG];   // in_q_w^T      [o][i]
__device__ float g_ikT[CIMG*CIMG];   // in_k_w^T      [c][i]
__device__ float g_ivT[CIMG*CIMG];   // in_v_w^T      [c][i]
__device__ float g_ocT[CIMG*CIMG];   // out_conv_w^T  [j][co]
__device__ float g_KH[BQ*LTXT*CIMG]; // [b,l,i]
__device__ float g_VH[BQ*LTXT*CIMG];
__device__ float g_Q [BQ*NTOK*CIMG]; // [b,h,n,hd]  HEAD-MAJOR for coalesced attention reads
__device__ float g_OT[BQ*CIMG*NTOK]; // [b,i,n]  (attention output, channel-major)
__device__ float g_R [BQ*CIMG*NTOK]; // [b,c,n]  residual sum pre-norm
__device__ float g_psum[BQ*CIMG];
__device__ float g_psumsq[BQ*CIMG];
__device__ float g_mean[BQ*CIMG];
__device__ float g_rstd[BQ*CIMG];
__device__ unsigned char g_mask[BQ*LTXT];  // normalized mask (dtype-agnostic)

// cp.async helpers (sm_80+; native LDGSTS on sm_103a)
#define CP_ASYNC16(smem_u32, gptr) \
    asm volatile("cp.async.cg.shared.global [%0], [%1], 16;\n" :: "r"(smem_u32), "l"(gptr))
#define CP_COMMIT()  asm volatile("cp.async.commit_group;\n" ::: "memory")
#define CP_WAIT0()   asm volatile("cp.async.wait_group 0;\n" ::: "memory")

// packed f32x2 FMA (Blackwell): d = a*b + d on two lanes at once
#define FFMA2(d, a, b) \
    asm("fma.rn.f32x2 %0, %1, %2, %0;" : "+l"(d) : "l"(a), "l"(b))
#define PACK2_BCAST(d, f) \
    asm("mov.b64 %0, {%1, %1};" : "=l"(d) : "r"(__float_as_uint(f)))

__device__ __forceinline__ unsigned smem_u32(const void* p) {
    return (unsigned)__cvta_generic_to_shared(p);
}
__device__ __forceinline__ float ull_lo(unsigned long long v) {
    return __uint_as_float((unsigned)(v & 0xffffffffull));
}
__device__ __forceinline__ float ull_hi(unsigned long long v) {
    return __uint_as_float((unsigned)(v >> 32));
}

// ---------------- mask normalization: accept uint8 OR int32 bool encoding ----
__global__ void k_mask(const unsigned char* __restrict__ mraw) {
    __shared__ int s_ok;
    if (threadIdx.x == 0) s_ok = 1;
    __syncthreads();
    int b = threadIdx.x;
    if (b < BQ) {
        int prev = 0, ok = 1;
        for (int l = 0; l < LTXT; l++) {
            int v = mraw[b*LTXT + l];
            if (v > 1 || v < prev) { ok = 0; break; }
            prev = v;
        }
        if (ok && mraw[b*LTXT + LTXT - 1] != 1) ok = 0;
        if (!ok) atomicExch(&s_ok, 0);
    }
    __syncthreads();
    if (b < BQ) {
        const int* m32 = (const int*)mraw;
        for (int l = 0; l < LTXT; l++) {
            g_mask[b*LTXT + l] = s_ok ? mraw[b*LTXT + l]
                                      : (unsigned char)(m32[b*LTXT + l] != 0);
        }
    }
}

// ---------------- setup kernels ----------------
__global__ void k_zero_stats() {
    int i = blockIdx.x * 256 + threadIdx.x;
    if (i < BQ*CIMG) { g_psum[i] = 0.f; g_psumsq[i] = 0.f; }
}

// 256x256 coalesced transpose: out[c][r] = in[r][c].  grid (8,8), block (32,8)
__global__ void k_transpose(const float* __restrict__ in, float* __restrict__ out) {
    __shared__ float tile[32][33];
    int bx = blockIdx.x * 32, by = blockIdx.y * 32;
    int x = threadIdx.x;
    for (int j = threadIdx.y; j < 32; j += 8)
        tile[j][x] = in[(by + j) * CIMG + bx + x];
    __syncthreads();
    for (int j = threadIdx.y; j < 32; j += 8)
        out[(bx + j) * CIMG + by + x] = tile[x][j];
}

// WqT[c,i] = sum_o iqT[o,i] * q_proj_w[o,c]   — 8 c per block, coalesced iqT reads
#define WTB 8
__global__ __launch_bounds__(256)
void k_wq2(const float* __restrict__ q_proj_w) {
    int c0 = blockIdx.x * WTB;
    int i  = threadIdx.x;
    __shared__ float sp[CIMG][WTB];
    for (int idx = threadIdx.x; idx < CIMG*WTB; idx += 256) {
        int o = idx >> 3, cj = idx & 7;
        sp[o][cj] = q_proj_w[o*CIMG + c0 + cj];
    }
    __syncthreads();
    float acc[WTB];
#pragma unroll
    for (int cj = 0; cj < WTB; cj++) acc[cj] = 0.f;
    for (int o = 0; o < CIMG; o++) {
        float w = g_iqT[o*CIMG + i];
#pragma unroll
        for (int cj = 0; cj < WTB; cj++) acc[cj] += w * sp[o][cj];
    }
#pragma unroll
    for (int cj = 0; cj < WTB; cj++) g_WqT[(c0 + cj)*CIMG + i] = acc[cj];
}

// WkT/WvT[t,i] = sum_c ikT/ivT[c,i] * proj[c,t]  — 8 t per block, both K and V in one pass
__global__ __launch_bounds__(256)
void k_wkv2(const float* __restrict__ k_proj_w, const float* __restrict__ v_proj_w) {
    int t0 = blockIdx.x * WTB;
    int i  = threadIdx.x;
    __shared__ float spk[CIMG][WTB];
    __shared__ float spv[CIMG][WTB];
    for (int idx = threadIdx.x; idx < CIMG*WTB; idx += 256) {
        int c = idx >> 3, tj = idx & 7;
        spk[c][tj] = k_proj_w[c*CTXT + t0 + tj];
        spv[c][tj] = v_proj_w[c*CTXT + t0 + tj];
    }
    __syncthreads();
    float ak[WTB], av[WTB];
#pragma unroll
    for (int tj = 0; tj < WTB; tj++) { ak[tj] = 0.f; av[tj] = 0.f; }
    for (int c = 0; c < CIMG; c++) {
        float wk = g_ikT[c*CIMG + i];
        float wv = g_ivT[c*CIMG + i];
#pragma unroll
        for (int tj = 0; tj < WTB; tj++) {
            ak[tj] += wk * spk[c][tj];
            av[tj] += wv * spv[c][tj];
        }
    }
#pragma unroll
    for (int tj = 0; tj < WTB; tj++) {
        g_WkT[(t0 + tj)*CIMG + i] = ak[tj];
        g_WvT[(t0 + tj)*CIMG + i] = av[tj];
    }
}

// WoT[i,co] = sum_j ocT[j,co] * out_proj_w[j,i]  — 8 i per block, coalesced ocT reads
__global__ __launch_bounds__(256)
void k_wo2(const float* __restrict__ out_proj_w) {
    int i0 = blockIdx.x * WTB;
    int co = threadIdx.x;
    __shared__ float sp[CIMG][WTB];
    for (int idx = threadIdx.x; idx < CIMG*WTB; idx += 256) {
        int j = idx >> 3, ij = idx & 7;
        sp[j][ij] = out_proj_w[j*CIMG + i0 + ij];
    }
    __syncthreads();
    float acc[WTB];
#pragma unroll
    for (int ij = 0; ij < WTB; ij++) acc[ij] = 0.f;
    for (int j = 0; j < CIMG; j++) {
        float w = g_ocT[j*CIMG + co];
#pragma unroll
        for (int ij = 0; ij < WTB; ij++) acc[ij] += w * sp[j][ij];
    }
#pragma unroll
    for (int ij = 0; ij < WTB; ij++) g_WoT[(i0 + ij)*CIMG + co] = acc[ij];
}

__global__ void k_biaso(const float* __restrict__ out_conv_w, const float* __restrict__ out_proj_b,
                        const float* __restrict__ out_conv_b) {
    int co = threadIdx.x;
    float s = out_conv_b[co];
    for (int j = 0; j < CIMG; j++) s += out_conv_w[co*CIMG + j] * out_proj_b[j];
    g_biaso[co] = s;
}

// ---------------- K/V projection: 8 text tokens per block (weight reuse x8) ----
#define KVTOK 8
__global__ __launch_bounds__(256)
void k_kv(const float* __restrict__ x_txt,
          const float* __restrict__ in_k_b, const float* __restrict__ in_v_b) {
    int b  = blockIdx.x / ((LTXT + KVTOK - 1) / KVTOK);
    int c0 = blockIdx.x % ((LTXT + KVTOK - 1) / KVTOK);
    int l0 = c0 * KVTOK;
    int nt = min(KVTOK, LTXT - l0);

    __shared__ float xr[KVTOK][CTXT];
    for (int idx = threadIdx.x; idx < nt * CTXT; idx += 256) {
        int j = idx / CTXT, t = idx % CTXT;
        xr[j][t] = x_txt[((long)b * LTXT + l0 + j) * CTXT + t];
    }
    __syncthreads();

    int i = threadIdx.x;
    float bk = in_k_b[i], bv = in_v_b[i];
    float sk[KVTOK], sv[KVTOK];
#pragma unroll
    for (int j = 0; j < KVTOK; j++) { sk[j] = bk; sv[j] = bv; }

    for (int t = 0; t < CTXT; t++) {
        float wk = g_WkT[t*CIMG + i];
        float wv = g_WvT[t*CIMG + i];
#pragma unroll
        for (int j = 0; j < KVTOK; j++) {
            float x = xr[j][t];
            sk[j] += x * wk;
            sv[j] += x * wv;
        }
    }
    for (int j = 0; j < nt; j++) {
        long o = ((long)b * LTXT + l0 + j) * CIMG + i;
        g_KH[o] = sk[j];
        g_VH[o] = sv[j];
    }
}

// ---------------- main GEMM: C[M,Nc] = sum_k A[k,m] * B[k,n]  (both k-major) ----------------
// Per-thread columns: 4 pairs at {jp*32 + tx*2, +1} — LDS.64 lanes contiguous
// (128 B span per 16 lanes) -> conflict-free shared loads; float2 epilogue stores.
#define GBM 128
#define GBN 128
#define GBK 16

template<int EPI>
__global__ __launch_bounds__(256)
void gemm_kn(const float* __restrict__ Ab, const float* __restrict__ Bb, float* __restrict__ Cb,
             int M, int Nc, int K, int lda, int ldb, int ldc,
             long sA, long sB, long sC,
             const float* __restrict__ biasN,
             const float* __restrict__ residB, long sR)
{
    int bz = blockIdx.z;
    const float* A = Ab + (long)bz * sA;
    const float* B = Bb + (long)bz * sB;
    float*       C = Cb + (long)bz * sC;

    __shared__ float As[2][GBK][GBM];
    __shared__ float Bs[2][GBK][GBN];

    int bm  = blockIdx.y * GBM;
    int bn  = blockIdx.x * GBN;
    int tid = threadIdx.x;
    int lr  = tid >> 5;           // 0..7
    int lc  = (tid & 31) << 2;    // col*4
    int ty  = tid >> 4;           // 0..15
    int tx  = tid & 15;           // 0..15
    int txc = tx << 1;            // column base within each 32-col group

    unsigned long long acc[8][4]; // 8 rows x 4 packed column-pairs (f32x2)
#pragma unroll
    for (int i = 0; i < 8; i++)
#pragma unroll
        for (int jp = 0; jp < 4; jp++) acc[i][jp] = 0ull;

    CP_ASYNC16(smem_u32(&As[0][lr    ][lc]), &A[(long)(lr    ) * lda + bm + lc]);
    CP_ASYNC16(smem_u32(&As[0][lr + 8][lc]), &A[(long)(lr + 8) * lda + bm + lc]);
    CP_ASYNC16(smem_u32(&Bs[0][lr    ][lc]), &B[(long)(lr    ) * ldb + bn + lc]);
    CP_ASYNC16(smem_u32(&Bs[0][lr + 8][lc]), &B[(long)(lr + 8) * ldb + bn + lc]);
    CP_COMMIT();
    CP_WAIT0();
    __syncthreads();

    int buf = 0;
    for (int k0 = 0; k0 < K; k0 += GBK) {
        bool more = (k0 + GBK < K);
        if (more) {
            int nb = buf ^ 1;
            CP_ASYNC16(smem_u32(&As[nb][lr    ][lc]), &A[(long)(k0 + GBK + lr    ) * lda + bm + lc]);
            CP_ASYNC16(smem_u32(&As[nb][lr + 8][lc]), &A[(long)(k0 + GBK + lr + 8) * lda + bm + lc]);
            CP_ASYNC16(smem_u32(&Bs[nb][lr    ][lc]), &B[(long)(k0 + GBK + lr    ) * ldb + bn + lc]);
            CP_ASYNC16(smem_u32(&Bs[nb][lr + 8][lc]), &B[(long)(k0 + GBK + lr + 8) * ldb + bn + lc]);
            CP_COMMIT();
        }

#pragma unroll
        for (int kk = 0; kk < GBK; kk++) {
            unsigned long long rbp[4];
#pragma unroll
            for (int jp = 0; jp < 4; jp++)
                rbp[jp] = *reinterpret_cast<const unsigned long long*>(&Bs[buf][kk][jp*32 + txc]);
#pragma unroll
            for (int i = 0; i < 8; i++) {
                unsigned long long rap;
                PACK2_BCAST(rap, As[buf][kk][ty*8 + i]);
#pragma unroll
                for (int jp = 0; jp < 4; jp++)
                    FFMA2(acc[i][jp], rap, rbp[jp]);
            }
        }

        if (more) {
            CP_WAIT0();
            __syncthreads();
            buf ^= 1;
        }
    }

    if (EPI == 0) {
        // head-major Q store: row = token n, col = channel i = h*32 + hd.
        // Both cols of a pair land in the same head (jp*32+txc, +1), so one float2 store.
#pragma unroll
        for (int i = 0; i < 8; i++) {
            int row = bm + ty*8 + i;
#pragma unroll
            for (int jp = 0; jp < 4; jp++) {
                int col0 = bn + jp*32 + txc;
                int h    = col0 >> 5;
                int hd   = col0 & 31;
                float2 v;
                v.x = ull_lo(acc[i][jp]) + biasN[col0];
                v.y = ull_hi(acc[i][jp]) + biasN[col0 + 1];
                *reinterpret_cast<float2*>(&C[((long)h * NTOK + row) * HDIM + hd]) = v;
            }
        }
    } else {
        const float* resid = residB + (long)bz * sR;
#pragma unroll
        for (int i = 0; i < 8; i++) {
            int row = bm + ty*8 + i;     // channel co (M=256)
            float bM = g_biaso[row];
            float rs = 0.f, rss = 0.f;
#pragma unroll
            for (int jp = 0; jp < 4; jp++) {
                int col0 = bn + jp*32 + txc;
                float2 r2 = *reinterpret_cast<const float2*>(&resid[(long)row * ldc + col0]);
                float2 v;
                v.x = ull_lo(acc[i][jp]) + bM + r2.x;
                v.y = ull_hi(acc[i][jp]) + bM + r2.y;
                *reinterpret_cast<float2*>(&C[(long)row * ldc + col0]) = v;
                rs  += v.x + v.y;
                rss += v.x * v.x + v.y * v.y;
            }
#pragma unroll
            for (int off = 8; off >= 1; off >>= 1) {
                rs  += __shfl_down_sync(0xffffffffu, rs,  off, 16);
                rss += __shfl_down_sync(0xffffffffu, rss, off, 16);
            }
            if (tx == 0) {
                atomicAdd(&g_psum[bz*CIMG + row],   rs);
                atomicAdd(&g_psumsq[bz*CIMG + row], rss);
            }
        }
    }
}

// ---------------- attention: one thread per query token, flash-style over L=77 ----------------
__global__ __launch_bounds__(256)
void k_attn() {
    int b = blockIdx.z, h = blockIdx.y;
    int n = blockIdx.x * 256 + threadIdx.x;

    __shared__ float Kh[LTXT][HDIM];
    __shared__ float Vh[LTXT][HDIM];
    __shared__ unsigned char ms[LTXT];

    for (int idx = threadIdx.x; idx < LTXT*HDIM; idx += 256) {
        int l = idx >> 5, j = idx & 31;
        Kh[l][j] = g_KH[(b*LTXT + l)*CIMG + h*HDIM + j];
        Vh[l][j] = g_VH[(b*LTXT + l)*CIMG + h*HDIM + j];
    }
    if (threadIdx.x < LTXT) ms[threadIdx.x] = g_mask[b*LTXT + threadIdx.x];
    __syncthreads();

    float q[HDIM];
    const float4* qp = reinterpret_cast<const float4*>(
        &g_Q[(((long)b * NHEAD + h) * NTOK + n) * HDIM]);
#pragma unroll
    for (int j4 = 0; j4 < 8; j4++) {
        float4 t = qp[j4];
        q[j4*4+0] = t.x; q[j4*4+1] = t.y; q[j4*4+2] = t.z; q[j4*4+3] = t.w;
    }

    float m = -1e30f, sum = 0.f;
    float o[HDIM];
#pragma unroll
    for (int j = 0; j < HDIM; j++) o[j] = 0.f;

    for (int l = 0; l < LTXT; l++) {
        if (ms[l]) continue;
        float s = 0.f;
#pragma unroll
        for (int j = 0; j < HDIM; j++) s += q[j] * Kh[l][j];
        s *= 0.17677669529663687f;            // 1/sqrt(32)
        float mn   = fmaxf(m, s);
        float corr = __expf(m - mn);
        float p    = __expf(s - mn);
        sum = sum * corr + p;
#pragma unroll
        for (int j = 0; j < HDIM; j++) o[j] = o[j] * corr + p * Vh[l][j];
        m = mn;
    }
    float inv = 1.f / sum;
    int obase = (b*CIMG + h*HDIM) * NTOK + n;
#pragma unroll
    for (int j = 0; j < HDIM; j++) g_OT[obase + j*NTOK] = o[j] * inv;
}

// ---------------- norm stats + finalize ----------------
__global__ void k_stats() {
    int i = blockIdx.x * 256 + threadIdx.x;
    if (i < BQ*CIMG) {
        float mu  = g_psum[i]   * (1.f / NTOK);
        float var = g_psumsq[i] * (1.f / NTOK) - mu * mu;
        g_mean[i] = mu;
        g_rstd[i] = rsqrtf(var + 1e-5f);
    }
}

__global__ __launch_bounds__(256)
void k_final(const float* __restrict__ nw, const float* __restrict__ nb, float* __restrict__ out) {
    int i4 = blockIdx.x * 256 + threadIdx.x;   // < TOTAL/4
    int i  = i4 * 4;
    int bc = i / NTOK;
    int c  = bc & (CIMG - 1);
    float mu = g_mean[bc], rs = g_rstd[bc], w = nw[c], bb = nb[c];
    float4 r = *reinterpret_cast<const float4*>(&g_R[i]);
    float4 o;
    float v;
    v = (r.x - mu) * rs * w + bb; o.x = v / (1.f + __expf(-v));
    v = (r.y - mu) * rs * w + bb; o.y = v / (1.f + __expf(-v));
    v = (r.z - mu) * rs * w + bb; o.z = v / (1.f + __expf(-v));
    v = (r.w - mu) * rs * w + bb; o.w = v / (1.f + __expf(-v));
    *reinterpret_cast<float4*>(&out[i]) = o;
}

// ---------------- launch ----------------
extern "C" void kernel_launch(void* const* d_in, const int* in_sizes, int n_in,
                              void* d_out, int out_size) {
    const float* x_img      = (const float*)d_in[0];
    const float* x_txt      = (const float*)d_in[1];
    const unsigned char* txt_mask = (const unsigned char*)d_in[2];
    const float* q_proj_w   = (const float*)d_in[3];
    const float* k_proj_w   = (const float*)d_in[4];
    const float* v_proj_w   = (const float*)d_in[5];
    const float* in_q_w     = (const float*)d_in[6];
    const float* in_q_b     = (const float*)d_in[7];
    const float* in_k_w     = (const float*)d_in[8];
    const float* in_k_b     = (const float*)d_in[9];
    const float* in_v_w     = (const float*)d_in[10];
    const float* in_v_b     = (const float*)d_in[11];
    const float* out_proj_w = (const float*)d_in[12];
    const float* out_proj_b = (const float*)d_in[13];
    const float* out_conv_w = (const float*)d_in[14];
    const float* out_conv_b = (const float*)d_in[15];
    const float* norm_w     = (const float*)d_in[16];
    const float* norm_b     = (const float*)d_in[17];
    float* out = (float*)d_out;

    float *pWqT, *pWoT, *pQ, *pOT, *pR, *piqT, *pikT, *pivT, *pocT;
    cudaGetSymbolAddress((void**)&pWqT, g_WqT);
    cudaGetSymbolAddress((void**)&pWoT, g_WoT);
    cudaGetSymbolAddress((void**)&pQ,   g_Q);
    cudaGetSymbolAddress((void**)&pOT,  g_OT);
    cudaGetSymbolAddress((void**)&pR,   g_R);
    cudaGetSymbolAddress((void**)&piqT, g_iqT);
    cudaGetSymbolAddress((void**)&pikT, g_ikT);
    cudaGetSymbolAddress((void**)&pivT, g_ivT);
    cudaGetSymbolAddress((void**)&pocT, g_ocT);

    k_zero_stats<<<(BQ*CIMG + 255)/256, 256>>>();
    k_mask<<<1, 32>>>(txt_mask);

    // transpose the four row-walked weight matrices (coalesced tiled transpose)
    {
        dim3 tg(8, 8), tb(32, 8);
        k_transpose<<<tg, tb>>>(in_q_w,     piqT);
        k_transpose<<<tg, tb>>>(in_k_w,     pikT);
        k_transpose<<<tg, tb>>>(in_v_w,     pivT);
        k_transpose<<<tg, tb>>>(out_conv_w, pocT);
    }

    // fused weights (all loads coalesced now)
    k_wq2  <<<CIMG/WTB, 256>>>(q_proj_w);
    k_wkv2 <<<CTXT/WTB, 256>>>(k_proj_w, v_proj_w);
    k_wo2  <<<CIMG/WTB, 256>>>(out_proj_w);
    k_biaso<<<1, CIMG>>>(out_conv_w, out_proj_b, out_conv_b);

    // K/V heads (8 tokens per block for weight reuse)
    k_kv<<<BQ * ((LTXT + KVTOK - 1) / KVTOK), 256>>>(x_txt, in_k_b, in_v_b);

    // Q = x_img^T @ Wq^T + bq  -> g_Q [b,h,n,hd] head-major
    {
        dim3 grid(CIMG/GBN, NTOK/GBM, BQ);
        gemm_kn<0><<<grid, 256>>>(x_img, pWqT, pQ,
                                  NTOK, CIMG, CIMG,
                                  NTOK, CIMG, CIMG,
                                  (long)CIMG*NTOK, 0L, (long)NTOK*CIMG,
                                  in_q_b, nullptr, 0L);
    }

    // attention -> g_OT [b,i,n]
    {
        dim3 grid(NTOK/256, NHEAD, BQ);
        k_attn<<<grid, 256>>>();
    }

    // R = Wo @ O + bias_o + x_img  -> g_R [b,c,n]  (+ per-channel stats)
    {
        dim3 grid(NTOK/GBN, CIMG/GBM, BQ);
        gemm_kn<1><<<grid, 256>>>(pWoT, pOT, pR,
                                  CIMG, NTOK, CIMG,
                                  CIMG, NTOK, NTOK,
                                  0L, (long)CIMG*NTOK, (long)CIMG*NTOK,
                                  nullptr, x_img, (long)CIMG*NTOK);
    }

    k_stats<<<(BQ*CIMG + 255)/256, 256>>>();
    k_final<<<TOTAL/1024, 256>>>(norm_w, norm_b, out);
}

// round 15
// speedup vs baseline: 1.6051x; 1.0458x over previous
#include <cuda_runtime.h>
#include <math.h>

#define BQ    8
#define CIMG  256
#define CTXT  768
#define NHEAD 8
#define HDIM  32
#define LTXT  77
#define NTOK  13824
#define TOTAL (BQ*CIMG*NTOK)

__device__ float g_WqT[CIMG*CIMG];
__device__ float g_WkT[CTXT*CIMG];
__device__ float g_WvT[CTXT*CIMG];
__device__ float g_WoT[CIMG*CIMG];
__device__ float g_biaso[CIMG];
__device__ float g_iqT[CIMG*CIMG];
__device__ float g_ikT[CIMG*CIMG];
__device__ float g_ivT[CIMG*CIMG];
__device__ float g_ocT[CIMG*CIMG];
__device__ float g_KH[BQ*LTXT*CIMG];
__device__ float g_VH[BQ*LTXT*CIMG];
__device__ float g_Q [BQ*NTOK*CIMG];   // head-major [b,h,n,hd]
__device__ float g_OT[BQ*CIMG*NTOK];   // [b,i,n]
__device__ float g_R [BQ*CIMG*NTOK];   // [b,c,n]
__device__ float g_psum[BQ*CIMG];
__device__ float g_psumsq[BQ*CIMG];
__device__ float g_mean[BQ*CIMG];
__device__ float g_rstd[BQ*CIMG];
__device__ unsigned char g_mask[BQ*LTXT];

#define CP_ASYNC16(smem_u32, gptr) \
    asm volatile("cp.async.cg.shared.global [%0], [%1], 16;\n" :: "r"(smem_u32), "l"(gptr))
#define CP_COMMIT()  asm volatile("cp.async.commit_group;\n" ::: "memory")
#define CP_WAIT0()   asm volatile("cp.async.wait_group 0;\n" ::: "memory")

#define FFMA2(d, a, b) \
    asm("fma.rn.f32x2 %0, %1, %2, %0;" : "+l"(d) : "l"(a), "l"(b))
#define MUL2(d, a, b) \
    asm("mul.rn.f32x2 %0, %1, %2;" : "=l"(d) : "l"(a), "l"(b))
#define PACK2_BCAST(d, f) \
    asm("mov.b64 %0, {%1, %1};" : "=l"(d) : "r"(__float_as_uint(f)))

__device__ __forceinline__ unsigned smem_u32(const void* p) {
    return (unsigned)__cvta_generic_to_shared(p);
}
__device__ __forceinline__ float ull_lo(unsigned long long v) {
    return __uint_as_float((unsigned)(v & 0xffffffffull));
}
__device__ __forceinline__ float ull_hi(unsigned long long v) {
    return __uint_as_float((unsigned)(v >> 32));
}

// mask normalization: accept uint8 OR int32 bool encoding (rows are monotone 0->1)
__global__ void k_mask(const unsigned char* __restrict__ mraw) {
    __shared__ int s_ok;
    if (threadIdx.x == 0) s_ok = 1;
    __syncthreads();
    int b = threadIdx.x;
    if (b < BQ) {
        int prev = 0, ok = 1;
        for (int l = 0; l < LTXT; l++) {
            int v = mraw[b*LTXT + l];
            if (v > 1 || v < prev) { ok = 0; break; }
            prev = v;
        }
        if (ok && mraw[b*LTXT + LTXT - 1] != 1) ok = 0;
        if (!ok) atomicExch(&s_ok, 0);
    }
    __syncthreads();
    if (b < BQ) {
        const int* m32 = (const int*)mraw;
        for (int l = 0; l < LTXT; l++) {
            g_mask[b*LTXT + l] = s_ok ? mraw[b*LTXT + l]
                                      : (unsigned char)(m32[b*LTXT + l] != 0);
        }
    }
}

__global__ void k_zero_stats() {
    int i = blockIdx.x * 256 + threadIdx.x;
    if (i < BQ*CIMG) { g_psum[i] = 0.f; g_psumsq[i] = 0.f; }
}

// 256x256 coalesced transpose: out[c][r] = in[r][c].  grid (8,8), block (32,8)
__global__ void k_transpose(const float* __restrict__ in, float* __restrict__ out) {
    __shared__ float tile[32][33];
    int bx = blockIdx.x * 32, by = blockIdx.y * 32;
    int x = threadIdx.x;
    for (int j = threadIdx.y; j < 32; j += 8)
        tile[j][x] = in[(by + j) * CIMG + bx + x];
    __syncthreads();
    for (int j = threadIdx.y; j < 32; j += 8)
        out[(bx + j) * CIMG + by + x] = tile[x][j];
}

#define WTB 8
__global__ __launch_bounds__(256)
void k_wq2(const float* __restrict__ q_proj_w) {
    int c0 = blockIdx.x * WTB;
    int i  = threadIdx.x;
    __shared__ float sp[CIMG][WTB];
    for (int idx = threadIdx.x; idx < CIMG*WTB; idx += 256) {
        int o = idx >> 3, cj = idx & 7;
        sp[o][cj] = q_proj_w[o*CIMG + c0 + cj];
    }
    __syncthreads();
    float acc[WTB];
#pragma unroll
    for (int cj = 0; cj < WTB; cj++) acc[cj] = 0.f;
    for (int o = 0; o < CIMG; o++) {
        float w = g_iqT[o*CIMG + i];
#pragma unroll
        for (int cj = 0; cj < WTB; cj++) acc[cj] += w * sp[o][cj];
    }
#pragma unroll
    for (int cj = 0; cj < WTB; cj++) g_WqT[(c0 + cj)*CIMG + i] = acc[cj];
}

__global__ __launch_bounds__(256)
void k_wkv2(const float* __restrict__ k_proj_w, const float* __restrict__ v_proj_w) {
    int t0 = blockIdx.x * WTB;
    int i  = threadIdx.x;
    __shared__ float spk[CIMG][WTB];
    __shared__ float spv[CIMG][WTB];
    for (int idx = threadIdx.x; idx < CIMG*WTB; idx += 256) {
        int c = idx >> 3, tj = idx & 7;
        spk[c][tj] = k_proj_w[c*CTXT + t0 + tj];
        spv[c][tj] = v_proj_w[c*CTXT + t0 + tj];
    }
    __syncthreads();
    float ak[WTB], av[WTB];
#pragma unroll
    for (int tj = 0; tj < WTB; tj++) { ak[tj] = 0.f; av[tj] = 0.f; }
    for (int c = 0; c < CIMG; c++) {
        float wk = g_ikT[c*CIMG + i];
        float wv = g_ivT[c*CIMG + i];
#pragma unroll
        for (int tj = 0; tj < WTB; tj++) {
            ak[tj] += wk * spk[c][tj];
            av[tj] += wv * spv[c][tj];
        }
    }
#pragma unroll
    for (int tj = 0; tj < WTB; tj++) {
        g_WkT[(t0 + tj)*CIMG + i] = ak[tj];
        g_WvT[(t0 + tj)*CIMG + i] = av[tj];
    }
}

__global__ __launch_bounds__(256)
void k_wo2(const float* __restrict__ out_proj_w) {
    int i0 = blockIdx.x * WTB;
    int co = threadIdx.x;
    __shared__ float sp[CIMG][WTB];
    for (int idx = threadIdx.x; idx < CIMG*WTB; idx += 256) {
        int j = idx >> 3, ij = idx & 7;
        sp[j][ij] = out_proj_w[j*CIMG + i0 + ij];
    }
    __syncthreads();
    float acc[WTB];
#pragma unroll
    for (int ij = 0; ij < WTB; ij++) acc[ij] = 0.f;
    for (int j = 0; j < CIMG; j++) {
        float w = g_ocT[j*CIMG + co];
#pragma unroll
        for (int ij = 0; ij < WTB; ij++) acc[ij] += w * sp[j][ij];
    }
#pragma unroll
    for (int ij = 0; ij < WTB; ij++) g_WoT[(i0 + ij)*CIMG + co] = acc[ij];
}

__global__ void k_biaso(const float* __restrict__ out_conv_w, const float* __restrict__ out_proj_b,
                        const float* __restrict__ out_conv_b) {
    int co = threadIdx.x;
    float s = out_conv_b[co];
    for (int j = 0; j < CIMG; j++) s += out_conv_w[co*CIMG + j] * out_proj_b[j];
    g_biaso[co] = s;
}

#define KVTOK 8
__global__ __launch_bounds__(256)
void k_kv(const float* __restrict__ x_txt,
          const float* __restrict__ in_k_b, const float* __restrict__ in_v_b) {
    int b  = blockIdx.x / ((LTXT + KVTOK - 1) / KVTOK);
    int c0 = blockIdx.x % ((LTXT + KVTOK - 1) / KVTOK);
    int l0 = c0 * KVTOK;
    int nt = min(KVTOK, LTXT - l0);

    __shared__ float xr[KVTOK][CTXT];
    for (int idx = threadIdx.x; idx < nt * CTXT; idx += 256) {
        int j = idx / CTXT, t = idx % CTXT;
        xr[j][t] = x_txt[((long)b * LTXT + l0 + j) * CTXT + t];
    }
    __syncthreads();

    int i = threadIdx.x;
    float bk = in_k_b[i], bv = in_v_b[i];
    float sk[KVTOK], sv[KVTOK];
#pragma unroll
    for (int j = 0; j < KVTOK; j++) { sk[j] = bk; sv[j] = bv; }

    for (int t = 0; t < CTXT; t++) {
        float wk = g_WkT[t*CIMG + i];
        float wv = g_WvT[t*CIMG + i];
#pragma unroll
        for (int j = 0; j < KVTOK; j++) {
            float x = xr[j][t];
            sk[j] += x * wk;
            sv[j] += x * wv;
        }
    }
    for (int j = 0; j < nt; j++) {
        long o = ((long)b * LTXT + l0 + j) * CIMG + i;
        g_KH[o] = sk[j];
        g_VH[o] = sv[j];
    }
}

// main GEMM: C[M,Nc] = sum_k A[k,m] * B[k,n]  (both k-major)
// 128x128 tile, BK=16, 256 threads, 8x8 per thread as packed f32x2 pairs.
// cp.async ping-pong; conflict-free LDS.64; float2 epilogue stores.
#define GBM 128
#define GBN 128
#define GBK 16

template<int EPI>
__global__ __launch_bounds__(256)
void gemm_kn(const float* __restrict__ Ab, const float* __restrict__ Bb, float* __restrict__ Cb,
             int M, int Nc, int K, int lda, int ldb, int ldc,
             long sA, long sB, long sC,
             const float* __restrict__ biasN,
             const float* __restrict__ residB, long sR)
{
    int bz = blockIdx.z;
    const float* A = Ab + (long)bz * sA;
    const float* B = Bb + (long)bz * sB;
    float*       C = Cb + (long)bz * sC;

    __shared__ float As[2][GBK][GBM];
    __shared__ float Bs[2][GBK][GBN];

    int bm  = blockIdx.y * GBM;
    int bn  = blockIdx.x * GBN;
    int tid = threadIdx.x;
    int lr  = tid >> 5;
    int lc  = (tid & 31) << 2;
    int ty  = tid >> 4;
    int tx  = tid & 15;
    int txc = tx << 1;

    unsigned long long acc[8][4];
#pragma unroll
    for (int i = 0; i < 8; i++)
#pragma unroll
        for (int jp = 0; jp < 4; jp++) acc[i][jp] = 0ull;

    CP_ASYNC16(smem_u32(&As[0][lr    ][lc]), &A[(long)(lr    ) * lda + bm + lc]);
    CP_ASYNC16(smem_u32(&As[0][lr + 8][lc]), &A[(long)(lr + 8) * lda + bm + lc]);
    CP_ASYNC16(smem_u32(&Bs[0][lr    ][lc]), &B[(long)(lr    ) * ldb + bn + lc]);
    CP_ASYNC16(smem_u32(&Bs[0][lr + 8][lc]), &B[(long)(lr + 8) * ldb + bn + lc]);
    CP_COMMIT();
    CP_WAIT0();
    __syncthreads();

    int buf = 0;
    for (int k0 = 0; k0 < K; k0 += GBK) {
        bool more = (k0 + GBK < K);
        if (more) {
            int nb = buf ^ 1;
            CP_ASYNC16(smem_u32(&As[nb][lr    ][lc]), &A[(long)(k0 + GBK + lr    ) * lda + bm + lc]);
            CP_ASYNC16(smem_u32(&As[nb][lr + 8][lc]), &A[(long)(k0 + GBK + lr + 8) * lda + bm + lc]);
            CP_ASYNC16(smem_u32(&Bs[nb][lr    ][lc]), &B[(long)(k0 + GBK + lr    ) * ldb + bn + lc]);
            CP_ASYNC16(smem_u32(&Bs[nb][lr + 8][lc]), &B[(long)(k0 + GBK + lr + 8) * ldb + bn + lc]);
            CP_COMMIT();
        }

#pragma unroll
        for (int kk = 0; kk < GBK; kk++) {
            unsigned long long rbp[4];
#pragma unroll
            for (int jp = 0; jp < 4; jp++)
                rbp[jp] = *reinterpret_cast<const unsigned long long*>(&Bs[buf][kk][jp*32 + txc]);
#pragma unroll
            for (int i = 0; i < 8; i++) {
                unsigned long long rap;
                PACK2_BCAST(rap, As[buf][kk][ty*8 + i]);
#pragma unroll
                for (int jp = 0; jp < 4; jp++)
                    FFMA2(acc[i][jp], rap, rbp[jp]);
            }
        }

        if (more) {
            CP_WAIT0();
            __syncthreads();
            buf ^= 1;
        }
    }

    if (EPI == 0) {
        // head-major Q store: row = token n, col = channel i = h*32 + hd
#pragma unroll
        for (int i = 0; i < 8; i++) {
            int row = bm + ty*8 + i;
#pragma unroll
            for (int jp = 0; jp < 4; jp++) {
                int col0 = bn + jp*32 + txc;
                int h    = col0 >> 5;
                int hd   = col0 & 31;
                float2 v;
                v.x = ull_lo(acc[i][jp]) + biasN[col0];
                v.y = ull_hi(acc[i][jp]) + biasN[col0 + 1];
                *reinterpret_cast<float2*>(&C[((long)h * NTOK + row) * HDIM + hd]) = v;
            }
        }
    } else {
        const float* resid = residB + (long)bz * sR;
#pragma unroll
        for (int i = 0; i < 8; i++) {
            int row = bm + ty*8 + i;
            float bM = g_biaso[row];
            float rs = 0.f, rss = 0.f;
#pragma unroll
            for (int jp = 0; jp < 4; jp++) {
                int col0 = bn + jp*32 + txc;
                float2 r2 = *reinterpret_cast<const float2*>(&resid[(long)row * ldc + col0]);
                float2 v;
                v.x = ull_lo(acc[i][jp]) + bM + r2.x;
                v.y = ull_hi(acc[i][jp]) + bM + r2.y;
                *reinterpret_cast<float2*>(&C[(long)row * ldc + col0]) = v;
                rs  += v.x + v.y;
                rss += v.x * v.x + v.y * v.y;
            }
#pragma unroll
            for (int off = 8; off >= 1; off >>= 1) {
                rs  += __shfl_down_sync(0xffffffffu, rs,  off, 16);
                rss += __shfl_down_sync(0xffffffffu, rss, off, 16);
            }
            if (tx == 0) {
                atomicAdd(&g_psum[bz*CIMG + row],   rs);
                atomicAdd(&g_psumsq[bz*CIMG + row], rss);
            }
        }
    }
}

// attention: one thread per query token, packed f32x2 math.
// Q head-major [b,h,n,hd]; K/V staged in smem as 8-byte pairs (broadcast LDS.64).
__global__ __launch_bounds__(256)
void k_attn() {
    int b = blockIdx.z, h = blockIdx.y;
    int n = blockIdx.x * 256 + threadIdx.x;

    __shared__ unsigned long long Kh[LTXT][HDIM/2];
    __shared__ unsigned long long Vh[LTXT][HDIM/2];
    __shared__ unsigned char ms[LTXT];

    for (int idx = threadIdx.x; idx < LTXT*(HDIM/2); idx += 256) {
        int l = idx >> 4, j = idx & 15;
        Kh[l][j] = *reinterpret_cast<const unsigned long long*>(
            &g_KH[(b*LTXT + l)*CIMG + h*HDIM + j*2]);
        Vh[l][j] = *reinterpret_cast<const unsigned long long*>(
            &g_VH[(b*LTXT + l)*CIMG + h*HDIM + j*2]);
    }
    if (threadIdx.x < LTXT) ms[threadIdx.x] = g_mask[b*LTXT + threadIdx.x];
    __syncthreads();

    unsigned long long q2[HDIM/2];
    const unsigned long long* qp = reinterpret_cast<const unsigned long long*>(
        &g_Q[(((long)b * NHEAD + h) * NTOK + n) * HDIM]);
#pragma unroll
    for (int j = 0; j < HDIM/2; j++) q2[j] = qp[j];

    float m = -1e30f, sum = 0.f;
    unsigned long long o2[HDIM/2];
#pragma unroll
    for (int j = 0; j < HDIM/2; j++) o2[j] = 0ull;

    for (int l = 0; l < LTXT; l++) {
        if (ms[l]) continue;                    // uniform across block (per-batch mask)
        unsigned long long d2 = 0ull;
#pragma unroll
        for (int j = 0; j < HDIM/2; j++) FFMA2(d2, q2[j], Kh[l][j]);
        float s = (ull_lo(d2) + ull_hi(d2)) * 0.17677669529663687f;  // 1/sqrt(32)
        float mn   = fmaxf(m, s);
        float corr = __expf(m - mn);
        float p    = __expf(s - mn);
        sum = sum * corr + p;
        unsigned long long corr2, pp;
        PACK2_BCAST(corr2, corr);
        PACK2_BCAST(pp, p);
#pragma unroll
        for (int j = 0; j < HDIM/2; j++) {
            MUL2(o2[j], o2[j], corr2);
            FFMA2(o2[j], pp, Vh[l][j]);
        }
        m = mn;
    }
    float inv = 1.f / sum;
    int obase = (b*CIMG + h*HDIM) * NTOK + n;
#pragma unroll
    for (int j = 0; j < HDIM/2; j++) {
        g_OT[obase + (j*2    )*NTOK] = ull_lo(o2[j]) * inv;
        g_OT[obase + (j*2 + 1)*NTOK] = ull_hi(o2[j]) * inv;
    }
}

__global__ void k_stats() {
    int i = blockIdx.x * 256 + threadIdx.x;
    if (i < BQ*CIMG) {
        float mu  = g_psum[i]   * (1.f / NTOK);
        float var = g_psumsq[i] * (1.f / NTOK) - mu * mu;
        g_mean[i] = mu;
        g_rstd[i] = rsqrtf(var + 1e-5f);
    }
}

__global__ __launch_bounds__(256)
void k_final(const float* __restrict__ nw, const float* __restrict__ nb, float* __restrict__ out) {
    int i4 = blockIdx.x * 256 + threadIdx.x;
    int i  = i4 * 4;
    int bc = i / NTOK;
    int c  = bc & (CIMG - 1);
    float mu = g_mean[bc], rs = g_rstd[bc], w = nw[c], bb = nb[c];
    float4 r = *reinterpret_cast<const float4*>(&g_R[i]);
    float4 o;
    float v;
    v = (r.x - mu) * rs * w + bb; o.x = v / (1.f + __expf(-v));
    v = (r.y - mu) * rs * w + bb; o.y = v / (1.f + __expf(-v));
    v = (r.z - mu) * rs * w + bb; o.z = v / (1.f + __expf(-v));
    v = (r.w - mu) * rs * w + bb; o.w = v / (1.f + __expf(-v));
    *reinterpret_cast<float4*>(&out[i]) = o;
}

extern "C" void kernel_launch(void* const* d_in, const int* in_sizes, int n_in,
                              void* d_out, int out_size) {
    const float* x_img      = (const float*)d_in[0];
    const float* x_txt      = (const float*)d_in[1];
    const unsigned char* txt_mask = (const unsigned char*)d_in[2];
    const float* q_proj_w   = (const float*)d_in[3];
    const float* k_proj_w   = (const float*)d_in[4];
    const float* v_proj_w   = (const float*)d_in[5];
    const float* in_q_w     = (const float*)d_in[6];
    const float* in_q_b     = (const float*)d_in[7];
    const float* in_k_w     = (const float*)d_in[8];
    const float* in_k_b     = (const float*)d_in[9];
    const float* in_v_w     = (const float*)d_in[10];
    const float* in_v_b     = (const float*)d_in[11];
    const float* out_proj_w = (const float*)d_in[12];
    const float* out_proj_b = (const float*)d_in[13];
    const float* out_conv_w = (const float*)d_in[14];
    const float* out_conv_b = (const float*)d_in[15];
    const float* norm_w     = (const float*)d_in[16];
    const float* norm_b     = (const float*)d_in[17];
    float* out = (float*)d_out;

    float *pWqT, *pWoT, *pQ, *pOT, *pR, *piqT, *pikT, *pivT, *pocT;
    cudaGetSymbolAddress((void**)&pWqT, g_WqT);
    cudaGetSymbolAddress((void**)&pWoT, g_WoT);
    cudaGetSymbolAddress((void**)&pQ,   g_Q);
    cudaGetSymbolAddress((void**)&pOT,  g_OT);
    cudaGetSymbolAddress((void**)&pR,   g_R);
    cudaGetSymbolAddress((void**)&piqT, g_iqT);
    cudaGetSymbolAddress((void**)&pikT, g_ikT);
    cudaGetSymbolAddress((void**)&pivT, g_ivT);
    cudaGetSymbolAddress((void**)&pocT, g_ocT);

    k_zero_stats<<<(BQ*CIMG + 255)/256, 256>>>();
    k_mask<<<1, 32>>>(txt_mask);

    {
        dim3 tg(8, 8), tb(32, 8);
        k_transpose<<<tg, tb>>>(in_q_w,     piqT);
        k_transpose<<<tg, tb>>>(in_k_w,     pikT);
        k_transpose<<<tg, tb>>>(in_v_w,     pivT);
        k_transpose<<<tg, tb>>>(out_conv_w, pocT);
    }

    k_wq2  <<<CIMG/WTB, 256>>>(q_proj_w);
    k_wkv2 <<<CTXT/WTB, 256>>>(k_proj_w, v_proj_w);
    k_wo2  <<<CIMG/WTB, 256>>>(out_proj_w);
    k_biaso<<<1, CIMG>>>(out_conv_w, out_proj_b, out_conv_b);

    k_kv<<<BQ * ((LTXT + KVTOK - 1) / KVTOK), 256>>>(x_txt, in_k_b, in_v_b);

    {
        dim3 grid(CIMG/GBN, NTOK/GBM, BQ);
        gemm_kn<0><<<grid, 256>>>(x_img, pWqT, pQ,
                                  NTOK, CIMG, CIMG,
                                  NTOK, CIMG, CIMG,
                                  (long)CIMG*NTOK, 0L, (long)NTOK*CIMG,
                                  in_q_b, nullptr, 0L);
    }

    {
        dim3 grid(NTOK/256, NHEAD, BQ);
        k_attn<<<grid, 256>>>();
    }

    {
        dim3 grid(NTOK/GBN, CIMG/GBM, BQ);
        gemm_kn<1><<<grid, 256>>>(pWoT, pOT, pR,
                                  CIMG, NTOK, CIMG,
                                  CIMG, NTOK, NTOK,
                                  0L, (long)CIMG*NTOK, (long)CIMG*NTOK,
                                  nullptr, x_img, (long)CIMG*NTOK);
    }

    k_stats<<<(BQ*CIMG + 255)/256, 256>>>();
    k_final<<<TOTAL/1024, 256>>>(norm_w, norm_b, out);
}